// round 5
// baseline (speedup 1.0000x reference)
#include <cuda_runtime.h>
#include <cstdint>
#include <math.h>

#define EPSV 1e-4f
#define BROWS 8192
#define FDIM 512
#define PDIM 64
#define CDIM 100

typedef unsigned long long ull;

// ---- packed f32x2 helpers (ptxas emits FFMA2 only via PTX) ----
__device__ __forceinline__ ull pk2(float lo, float hi) {
    ull r; asm("mov.b64 %0, {%1, %2};" : "=l"(r) : "f"(lo), "f"(hi)); return r;
}
__device__ __forceinline__ float2 upk2(ull v) {
    float2 r; asm("mov.b64 {%0, %1}, %2;" : "=f"(r.x), "=f"(r.y) : "l"(v)); return r;
}
__device__ __forceinline__ ull fma2(ull a, ull b, ull c) {
    ull d; asm("fma.rn.f32x2 %0, %1, %2, %3;" : "=l"(d) : "l"(a), "l"(b), "l"(c)); return d;
}
__device__ __forceinline__ ull mul2(ull a, ull b) {
    ull d; asm("mul.rn.f32x2 %0, %1, %2;" : "=l"(d) : "l"(a), "l"(b)); return d;
}
__device__ __forceinline__ ull add2(ull a, ull b) {
    ull d; asm("add.rn.f32x2 %0, %1, %2;" : "=l"(d) : "l"(a), "l"(b)); return d;
}
__device__ __forceinline__ float frcp(float x) {
    float r; asm("rcp.approx.f32 %0, %1;" : "=f"(r) : "f"(x)); return r;
}
__device__ __forceinline__ unsigned int s2u(const void* p) {
    return (unsigned int)__cvta_generic_to_shared(p);
}
__device__ __forceinline__ void cpa16(unsigned int dst, const void* src) {
    asm volatile("cp.async.cg.shared.global [%0], [%1], 16;" :: "r"(dst), "l"(src));
}

// ---- dynamic smem layout (bytes) ----
#define SM_XS0 0          // 8 KB  (x chunk, buf 0)
#define SM_XS1 8192       // 8 KB
#define SM_WS0 16384      // 16 KB (w chunk, buf 0)
#define SM_WS1 32768      // 16 KB
#define SM_U   49152      // 64*112*4 = 28672
#define SM_SI  77824      // 32*68*4 = 8704 (stride 68: 16B-aligned float4 rows)
#define SM_CON 86528      // gam/alp/wn: 3*64*4 = 768
#define SM_OUT 0          // 32*102*4 = 13056, aliases dead xs buffers
#define SM_TOT 87296

__device__ __forceinline__ void stage_chunk(char* smem, int buf,
                                            const float* __restrict__ x,
                                            const float* __restrict__ w,
                                            int r0, int kc, int tid) {
    float* xsb = (float*)(smem + (buf ? SM_XS1 : SM_XS0));
    float* wsb = (float*)(smem + (buf ? SM_WS1 : SM_WS0));
    #pragma unroll
    for (int it = 0; it < 2; it++) {
        int f = tid + it * 256;
        int row = f >> 4, c = f & 15;
        unsigned int dst = s2u(xsb + (row << 6) + ((c * 4) ^ (((row >> 2) & 7) << 2)));
        cpa16(dst, x + (size_t)(r0 + row) * FDIM + kc + c * 4);
    }
    #pragma unroll
    for (int it = 0; it < 4; it++) {
        int f = tid + it * 256;
        int p = f >> 4, c = f & 15;
        unsigned int dst = s2u(wsb + (p << 6) + ((c * 4) ^ (((p >> 2) & 7) << 2)));
        cpa16(dst, w + (size_t)p * FDIM + kc + c * 4);
    }
    asm volatile("cp.async.commit_group;" ::: "memory");
}

__global__ __launch_bounds__(256, 2)
void fused_ds_kernel(const float* __restrict__ x, const float* __restrict__ w,
                     const float* __restrict__ xi, const float* __restrict__ eta,
                     const float* __restrict__ beta, float* __restrict__ out) {
    extern __shared__ __align__(16) char smem[];
    float* sU   = (float*)(smem + SM_U);
    float* sSi  = (float*)(smem + SM_SI);
    float* sGam = (float*)(smem + SM_CON);
    float* sAlp = sGam + 64;
    float* sWn  = sAlp + 64;
    float* sOut = (float*)(smem + SM_OUT);

    const int tid = threadIdx.x;
    const int r0  = blockIdx.x * 32;
    const unsigned FULL = 0xffffffffu;

    // kick off first GEMM chunk immediately
    stage_chunk(smem, 0, x, w, r0, 0, tid);

    // ---- phase 0: per-block constants (overlaps cp.async) ----
    if (tid < PDIM) {
        float e = eta[tid];
        sGam[tid] = e * e;
        sAlp[tid] = 1.f / (1.f + __expf(-xi[tid]));
    }
    {
        int wp = tid >> 5, l = tid & 31;
        #pragma unroll 1
        for (int rr = 0; rr < 8; rr++) {
            int row = wp * 8 + rr;
            const float* br = beta + (size_t)row * CDIM;
            float v0 = br[l],      bb0 = v0 * v0;
            float v1 = br[l + 32], bb1 = v1 * v1;
            float v2 = br[l + 64], bb2 = v2 * v2;
            float bb3 = 0.f;
            if (l < 4) { float v3 = br[l + 96]; bb3 = v3 * v3; }
            float s2 = bb0 + bb1 + bb2 + bb3;
            #pragma unroll
            for (int m = 16; m; m >>= 1) s2 += __shfl_xor_sync(FULL, s2, m);
            float rs = 1.f / s2;
            float* ur = sU + row * 112;
            ur[l] = bb0 * rs; ur[l + 32] = bb1 * rs; ur[l + 64] = bb2 * rs;
            if (l < 4) ur[l + 96] = bb3 * rs;
            if (l >= 4 && l < 16) ur[96 + l] = 0.f;   // zero-pad j=100..111
        }
    }

    // ---- phase A: GEMM, thread tile 2 rows x 4 protos ----
    const int rg = tid >> 4;   // rows rg*2 + {0,1}
    const int pg = tid & 15;   // protos pg*4 + {0..3}
    const int xorA = ((rg >> 1) & 7) << 2;   // == ((row>>2)&7)<<2 for both rows
    const int xorB = (pg & 7) << 2;          // == ((p>>2)&7)<<2 for all 4 protos

    ull acc[2][4];
    #pragma unroll
    for (int j = 0; j < 2; j++)
        #pragma unroll
        for (int i = 0; i < 4; i++) acc[j][i] = 0ull;
    ull xn2[2] = {0ull, 0ull};
    ull wn2 = 0ull;
    const int xorW = ((tid >> 2) & 7) << 2;

    #pragma unroll 1
    for (int ch = 0; ch < FDIM / 64; ch++) {
        const int buf = ch & 1;
        if (ch < FDIM / 64 - 1) {
            stage_chunk(smem, buf ^ 1, x, w, r0, (ch + 1) * 64, tid);
            asm volatile("cp.async.wait_group 1;" ::: "memory");
        } else {
            asm volatile("cp.async.wait_group 0;" ::: "memory");
        }
        __syncthreads();

        const float* xb = (const float*)(smem + (buf ? SM_XS1 : SM_XS0));
        const float* wb = (const float*)(smem + (buf ? SM_WS1 : SM_WS0));

        // wnorm partials from the staged w tile (threads 0..63, proto = tid)
        if (tid < PDIM) {
            const float* wr = wb + (tid << 6);
            #pragma unroll
            for (int c = 0; c < 16; c++) {
                ulonglong2 v = *(const ulonglong2*)(wr + ((c * 4) ^ xorW));
                wn2 = fma2(v.x, v.x, wn2);
                wn2 = fma2(v.y, v.y, wn2);
            }
        }

        #pragma unroll
        for (int kk = 0; kk < 64; kk += 4) {
            ulonglong2 a2[2], b2[4];
            #pragma unroll
            for (int j = 0; j < 2; j++)
                a2[j] = *(const ulonglong2*)(xb + ((rg * 2 + j) << 6) + (kk ^ xorA));
            #pragma unroll
            for (int i = 0; i < 4; i++)
                b2[i] = *(const ulonglong2*)(wb + ((pg * 4 + i) << 6) + (kk ^ xorB));
            #pragma unroll
            for (int j = 0; j < 2; j++) {
                xn2[j] = fma2(a2[j].x, a2[j].x, xn2[j]);
                xn2[j] = fma2(a2[j].y, a2[j].y, xn2[j]);
                #pragma unroll
                for (int i = 0; i < 4; i++) {
                    acc[j][i] = fma2(a2[j].x, b2[i].x, acc[j][i]);
                    acc[j][i] = fma2(a2[j].y, b2[i].y, acc[j][i]);
                }
            }
        }
        __syncthreads();
    }

    if (tid < PDIM) { float2 v = upk2(wn2); sWn[tid] = v.x + v.y; }
    __syncthreads();

    // ---- epilogue: si = exp(-gamma*d)*alpha, row-max normalize -> sSi ----
    #pragma unroll
    for (int j = 0; j < 2; j++) {
        const int row = rg * 2 + j;
        float2 xv = upk2(xn2[j]);
        const float xn = xv.x + xv.y;
        float sv[4];
        float mx = 0.f;
        #pragma unroll
        for (int i = 0; i < 4; i++) {
            int p = pg * 4 + i;
            float2 dv = upk2(acc[j][i]);
            float d = xn - 2.f * (dv.x + dv.y) + sWn[p];
            float si = __expf(-sGam[p] * d) * sAlp[p];
            sv[i] = si;
            mx = fmaxf(mx, si);
        }
        mx = fmaxf(mx, __shfl_xor_sync(FULL, mx, 1));
        mx = fmaxf(mx, __shfl_xor_sync(FULL, mx, 2));
        mx = fmaxf(mx, __shfl_xor_sync(FULL, mx, 4));
        mx = fmaxf(mx, __shfl_xor_sync(FULL, mx, 8));
        float inv = 1.f / (mx + EPSV);
        float4 o;
        o.x = sv[0] * inv; o.y = sv[1] * inv; o.z = sv[2] * inv; o.w = sv[3] * inv;
        *(float4*)(sSi + row * 68 + pg * 4) = o;
    }
    __syncthreads();

    // ---- phase B: Dempster scan (8 lanes/row, omega per-lane, norm every 4) ----
    const int lane = tid & 31;
    const int warp = tid >> 5;
    const int g = lane >> 3;          // row within warp
    const int q = lane & 7;           // element-lane: pairs j = 2q + 16i
    const int r = warp * 4 + g;
    const float* srow = sSi + r * 68;

    const ull fix6 = pk2((q == 2) ? 3.f : 1.f, 1.f);

    ull m[7];
    float om;
    {
        float s0 = srow[0];
        ull s0p = pk2(s0, s0);
        const float* u0 = sU + 2 * q;
        #pragma unroll
        for (int i = 0; i < 7; i++)
            m[i] = mul2(s0p, *(const ull*)(u0 + 16 * i));
        om = 1.f - s0;
        if (q == 2) m[6] = pk2(om, 0.f);
    }

    for (int p = 1; p < PDIM; p++) {
        float s = srow[p];
        float a = 1.f - s;
        float g1 = s * om;
        float om_new = 3.f * a * om;
        ull sp = pk2(s, s), ap = pk2(a, a), g1p = pk2(g1, g1);
        const float* up = sU + p * 112 + 2 * q;
        ull c[7];
        #pragma unroll
        for (int i = 0; i < 7; i++) {
            ull u2 = *(const ull*)(up + 16 * i);
            ull f  = fma2(sp, u2, ap);
            ull t  = mul2(m[i], f);
            c[i]   = fma2(g1p, u2, t);
        }
        c[6] = mul2(c[6], fix6);

        if ((p & 3) == 3) {
            ull ps = c[0];
            #pragma unroll
            for (int i = 1; i < 7; i++) ps = add2(ps, c[i]);
            float2 pv = upk2(ps);
            float psum = pv.x + pv.y;
            psum += __shfl_xor_sync(FULL, psum, 1);
            psum += __shfl_xor_sync(FULL, psum, 2);
            psum += __shfl_xor_sync(FULL, psum, 4);
            float rinv = frcp(psum);
            ull rp = pk2(rinv, rinv);
            #pragma unroll
            for (int i = 0; i < 7; i++) m[i] = mul2(c[i], rp);
            om = om_new * rinv;
        } else {
            #pragma unroll
            for (int i = 0; i < 7; i++) m[i] = c[i];
            om = om_new;
        }
    }

    // final exact normalization -> sOut
    {
        ull ps = m[0];
        #pragma unroll
        for (int i = 1; i < 7; i++) ps = add2(ps, m[i]);
        float2 pv = upk2(ps);
        float fs = pv.x + pv.y;
        fs += __shfl_xor_sync(FULL, fs, 1);
        fs += __shfl_xor_sync(FULL, fs, 2);
        fs += __shfl_xor_sync(FULL, fs, 4);
        float rn = 1.f / fs;

        float* orow = sOut + r * 102;
        #pragma unroll
        for (int i = 0; i < 6; i++) {
            float2 mv = upk2(m[i]);
            int j = 2 * q + 16 * i;
            *(float2*)(orow + j) = make_float2(mv.x * rn, mv.y * rn);
        }
        float2 mv = upk2(m[6]);
        int j = 96 + 2 * q;
        if (q < 2)       *(float2*)(orow + j) = make_float2(mv.x * rn, mv.y * rn);
        else if (q == 2) orow[100] = mv.x * rn;
    }
    __syncthreads();

    // coalesced output copy (block's 32 rows contiguous: 32*101 floats)
    for (int idx = tid; idx < 32 * (CDIM + 1); idx += 256) {
        int rr = idx / (CDIM + 1);
        int jj = idx - rr * (CDIM + 1);
        out[(size_t)r0 * (CDIM + 1) + idx] = sOut[rr * 102 + jj];
    }
}

extern "C" void kernel_launch(void* const* d_in, const int* in_sizes, int n_in,
                              void* d_out, int out_size) {
    const float* x    = (const float*)d_in[0];
    const float* w    = (const float*)d_in[1];
    const float* xi   = (const float*)d_in[2];
    const float* eta  = (const float*)d_in[3];
    const float* beta = (const float*)d_in[4];
    float* out = (float*)d_out;

    cudaFuncSetAttribute(fused_ds_kernel,
                         cudaFuncAttributeMaxDynamicSharedMemorySize, SM_TOT);
    fused_ds_kernel<<<BROWS / 32, 256, SM_TOT>>>(x, w, xi, eta, beta, out);
}

// round 6
// speedup vs baseline: 1.2002x; 1.2002x over previous
#include <cuda_runtime.h>
#include <cstdint>
#include <math.h>

#define EPSV 1e-4f
#define BROWS 8192
#define FDIM 512
#define PDIM 64
#define CDIM 100
#define USTRIDE 112

typedef unsigned long long ull;

__device__ float g_si[BROWS * PDIM];

// ---- packed f32x2 helpers ----
__device__ __forceinline__ ull pk2(float lo, float hi) {
    ull r; asm("mov.b64 %0, {%1, %2};" : "=l"(r) : "f"(lo), "f"(hi)); return r;
}
__device__ __forceinline__ float2 upk2(ull v) {
    float2 r; asm("mov.b64 {%0, %1}, %2;" : "=f"(r.x), "=f"(r.y) : "l"(v)); return r;
}
__device__ __forceinline__ ull fma2(ull a, ull b, ull c) {
    ull d; asm("fma.rn.f32x2 %0, %1, %2, %3;" : "=l"(d) : "l"(a), "l"(b), "l"(c)); return d;
}
__device__ __forceinline__ ull mul2(ull a, ull b) {
    ull d; asm("mul.rn.f32x2 %0, %1, %2;" : "=l"(d) : "l"(a), "l"(b)); return d;
}
__device__ __forceinline__ ull add2(ull a, ull b) {
    ull d; asm("add.rn.f32x2 %0, %1, %2;" : "=l"(d) : "l"(a), "l"(b)); return d;
}
__device__ __forceinline__ float frcp(float x) {
    float r; asm("rcp.approx.f32 %0, %1;" : "=f"(r) : "f"(x)); return r;
}
__device__ __forceinline__ unsigned int s2u(const void* p) {
    return (unsigned int)__cvta_generic_to_shared(p);
}
__device__ __forceinline__ void cpa16(unsigned int dst, const void* src) {
    asm volatile("cp.async.cg.shared.global [%0], [%1], 16;" :: "r"(dst), "l"(src));
}

// ================= GEMM + si (R4 config + inline wnorm/gamma/alpha) =================
#define GROWS 32
#define KC 64

__device__ __forceinline__ void stage_chunk(float* xsb, float* wsb,
                                            const float* __restrict__ x,
                                            const float* __restrict__ w,
                                            int r0, int kc, int tid) {
    #pragma unroll
    for (int it = 0; it < 8; it++) {
        int f = tid + it * 64;
        int row = f >> 4, c = f & 15;
        unsigned int dst = s2u(xsb + row * 64 + ((c * 4) ^ ((row >> 2) << 2)));
        cpa16(dst, x + (size_t)(r0 + row) * FDIM + kc + c * 4);
    }
    #pragma unroll
    for (int it = 0; it < 16; it++) {
        int f = tid + it * 64;
        int p = f >> 4, c = f & 15;
        unsigned int dst = s2u(wsb + p * 64 + ((c * 4) ^ ((p >> 3) << 2)));
        cpa16(dst, w + (size_t)p * FDIM + kc + c * 4);
    }
    asm volatile("cp.async.commit_group;" ::: "memory");
}

__global__ __launch_bounds__(64)
void gemm_si_kernel(const float* __restrict__ x, const float* __restrict__ w,
                    const float* __restrict__ xi, const float* __restrict__ eta) {
    __shared__ __align__(16) float xs[2][GROWS * KC];   // 2 x 8 KB
    __shared__ __align__(16) float ws[2][PDIM * KC];    // 2 x 16 KB
    __shared__ float sWn[PDIM];

    const int tid = threadIdx.x;
    const int r0  = blockIdx.x * GROWS;
    const int rg  = tid >> 3;   // 0..7 : rows rg*4 + j
    const int pg  = tid & 7;    // 0..7 : protos pg*8 + i

    // wnorm row assignment (bit-swap keeps LDS at bandwidth minimum)
    const int rw   = ((tid & 7) << 3) | (tid >> 3);
    const int xorW = (tid & 7) << 2;   // == (rw>>3)<<2

    ull acc[4][8];
    #pragma unroll
    for (int j = 0; j < 4; j++)
        #pragma unroll
        for (int i = 0; i < 8; i++) acc[j][i] = 0ull;
    ull xn2[4] = {0ull, 0ull, 0ull, 0ull};
    ull wn2 = 0ull;

    stage_chunk(xs[0], ws[0], x, w, r0, 0, tid);

    #pragma unroll 1
    for (int ch = 0; ch < FDIM / KC; ch++) {
        const int buf = ch & 1;
        if (ch < FDIM / KC - 1) {
            stage_chunk(xs[buf ^ 1], ws[buf ^ 1], x, w, r0, (ch + 1) * KC, tid);
            asm volatile("cp.async.wait_group 1;" ::: "memory");
        } else {
            asm volatile("cp.async.wait_group 0;" ::: "memory");
        }
        __syncthreads();

        const float* xb = xs[buf];
        const float* wb = ws[buf];

        // wnorm partials from staged w tile (thread tid owns proto rw)
        {
            const float* wr = wb + (rw << 6);
            #pragma unroll
            for (int c = 0; c < 16; c++) {
                ulonglong2 v = *(const ulonglong2*)(wr + ((c * 4) ^ xorW));
                wn2 = fma2(v.x, v.x, wn2);
                wn2 = fma2(v.y, v.y, wn2);
            }
        }

        #pragma unroll
        for (int kk = 0; kk < KC; kk += 4) {
            ulonglong2 a2[4], b2[8];
            #pragma unroll
            for (int j = 0; j < 4; j++)
                a2[j] = *(const ulonglong2*)(xb + ((rg * 4 + j) << 6) + (kk ^ (rg << 2)));
            #pragma unroll
            for (int i = 0; i < 8; i++)
                b2[i] = *(const ulonglong2*)(wb + ((pg * 8 + i) << 6) + (kk ^ (pg << 2)));
            #pragma unroll
            for (int j = 0; j < 4; j++) {
                xn2[j] = fma2(a2[j].x, a2[j].x, xn2[j]);
                xn2[j] = fma2(a2[j].y, a2[j].y, xn2[j]);
                #pragma unroll
                for (int i = 0; i < 8; i++) {
                    acc[j][i] = fma2(a2[j].x, b2[i].x, acc[j][i]);
                    acc[j][i] = fma2(a2[j].y, b2[i].y, acc[j][i]);
                }
            }
        }
        __syncthreads();
    }

    { float2 v = upk2(wn2); sWn[rw] = v.x + v.y; }
    __syncthreads();

    // per-thread gamma/alpha/wnorm for this thread's 8 protos
    float gam[8], alp[8], wnv[8];
    #pragma unroll
    for (int i = 0; i < 8; i++) {
        int p = pg * 8 + i;
        float e = __ldg(eta + p);
        gam[i] = e * e;
        alp[i] = 1.f / (1.f + __expf(-__ldg(xi + p)));
        wnv[i] = sWn[p];
    }

    // epilogue: si = exp(-gamma*d)*alpha, row-max normalize, store
    const unsigned FULL = 0xffffffffu;
    #pragma unroll
    for (int j = 0; j < 4; j++) {
        const int row = rg * 4 + j;
        float2 xv = upk2(xn2[j]);
        const float xn = xv.x + xv.y;
        float sv[8];
        float mx = 0.f;
        #pragma unroll
        for (int i = 0; i < 8; i++) {
            float2 dv = upk2(acc[j][i]);
            float d = xn - 2.f * (dv.x + dv.y) + wnv[i];
            float si = __expf(-gam[i] * d) * alp[i];
            sv[i] = si;
            mx = fmaxf(mx, si);
        }
        mx = fmaxf(mx, __shfl_xor_sync(FULL, mx, 1));
        mx = fmaxf(mx, __shfl_xor_sync(FULL, mx, 2));
        mx = fmaxf(mx, __shfl_xor_sync(FULL, mx, 4));
        float inv = 1.f / (mx + EPSV);
        float4 o0, o1;
        o0.x = sv[0] * inv; o0.y = sv[1] * inv; o0.z = sv[2] * inv; o0.w = sv[3] * inv;
        o1.x = sv[4] * inv; o1.y = sv[5] * inv; o1.z = sv[6] * inv; o1.w = sv[7] * inv;
        *(float4*)(g_si + (size_t)(r0 + row) * PDIM + pg * 8)     = o0;
        *(float4*)(g_si + (size_t)(r0 + row) * PDIM + pg * 8 + 4) = o1;
    }
}

// ================= Dempster scan (+ inline u computation) =================
#define SROWS 32
#define OSTRIDE 102

__global__ __launch_bounds__(256)
void scan_kernel(const float* __restrict__ beta, float* __restrict__ out) {
    __shared__ float sU[PDIM * USTRIDE];     // 28.7 KB
    __shared__ float sSi[SROWS * 65];        // 8.3 KB
    __shared__ float sOut[SROWS * OSTRIDE];  // 13.1 KB

    const int tid = threadIdx.x;
    const int r0  = blockIdx.x * SROWS;
    const unsigned FULL = 0xffffffffu;

    // stage si rows
    #pragma unroll
    for (int it = 0; it < 2; it++) {
        int f = tid + it * 256;
        int r = f >> 4, c = f & 15;
        float4 v = *(const float4*)(g_si + (size_t)(r0 + r) * PDIM + c * 4);
        sSi[r * 65 + c * 4 + 0] = v.x;
        sSi[r * 65 + c * 4 + 1] = v.y;
        sSi[r * 65 + c * 4 + 2] = v.z;
        sSi[r * 65 + c * 4 + 3] = v.w;
    }

    // per-block u table from beta (8 warps x 8 rows)
    {
        int wp = tid >> 5, l = tid & 31;
        #pragma unroll 1
        for (int rr = 0; rr < 8; rr++) {
            int row = wp * 8 + rr;
            const float* br = beta + (size_t)row * CDIM;
            float v0 = br[l],      bb0 = v0 * v0;
            float v1 = br[l + 32], bb1 = v1 * v1;
            float v2 = br[l + 64], bb2 = v2 * v2;
            float bb3 = 0.f;
            if (l < 4) { float v3 = br[l + 96]; bb3 = v3 * v3; }
            float s2 = bb0 + bb1 + bb2 + bb3;
            #pragma unroll
            for (int m = 16; m; m >>= 1) s2 += __shfl_xor_sync(FULL, s2, m);
            float rs = 1.f / s2;
            float* ur = sU + row * USTRIDE;
            ur[l] = bb0 * rs; ur[l + 32] = bb1 * rs; ur[l + 64] = bb2 * rs;
            if (l < 4) ur[l + 96] = bb3 * rs;
            if (l >= 4 && l < 16) ur[96 + l] = 0.f;   // zero-pad j=100..111
        }
    }
    __syncthreads();

    const int lane = tid & 31;
    const int warp = tid >> 5;
    const int g = lane >> 3;
    const int q = lane & 7;           // pairs j = 2q + 16i
    const int r = warp * 4 + g;
    const float* srow = sSi + r * 65;

    const ull fix6 = pk2((q == 2) ? 3.f : 1.f, 1.f);

    ull m[7];
    float om;
    {
        float s0 = srow[0];
        ull s0p = pk2(s0, s0);
        const float* u0 = sU + 2 * q;
        #pragma unroll
        for (int i = 0; i < 7; i++)
            m[i] = mul2(s0p, *(const ull*)(u0 + 16 * i));
        om = 1.f - s0;
        if (q == 2) m[6] = pk2(om, 0.f);
    }

    for (int p = 1; p < PDIM; p++) {
        float s = srow[p];
        float a = 1.f - s;
        float g1 = s * om;
        float om_new = 3.f * a * om;
        ull sp = pk2(s, s), ap = pk2(a, a), g1p = pk2(g1, g1);
        const float* up = sU + p * USTRIDE + 2 * q;
        ull c[7];
        #pragma unroll
        for (int i = 0; i < 7; i++) {
            ull u2 = *(const ull*)(up + 16 * i);
            ull f  = fma2(sp, u2, ap);
            ull t  = mul2(m[i], f);
            c[i]   = fma2(g1p, u2, t);
        }
        c[6] = mul2(c[6], fix6);

        if ((p & 3) == 3) {
            ull ps = c[0];
            #pragma unroll
            for (int i = 1; i < 7; i++) ps = add2(ps, c[i]);
            float2 pv = upk2(ps);
            float psum = pv.x + pv.y;
            psum += __shfl_xor_sync(FULL, psum, 1);
            psum += __shfl_xor_sync(FULL, psum, 2);
            psum += __shfl_xor_sync(FULL, psum, 4);
            float rinv = frcp(psum);
            ull rp = pk2(rinv, rinv);
            #pragma unroll
            for (int i = 0; i < 7; i++) m[i] = mul2(c[i], rp);
            om = om_new * rinv;
        } else {
            #pragma unroll
            for (int i = 0; i < 7; i++) m[i] = c[i];
            om = om_new;
        }
    }

    // final exact normalization
    {
        ull ps = m[0];
        #pragma unroll
        for (int i = 1; i < 7; i++) ps = add2(ps, m[i]);
        float2 pv = upk2(ps);
        float fs = pv.x + pv.y;
        fs += __shfl_xor_sync(FULL, fs, 1);
        fs += __shfl_xor_sync(FULL, fs, 2);
        fs += __shfl_xor_sync(FULL, fs, 4);
        float rn = 1.f / fs;

        float* orow = sOut + r * OSTRIDE;
        #pragma unroll
        for (int i = 0; i < 6; i++) {
            float2 mv = upk2(m[i]);
            int j = 2 * q + 16 * i;
            *(float2*)(orow + j) = make_float2(mv.x * rn, mv.y * rn);
        }
        float2 mv = upk2(m[6]);
        int j = 96 + 2 * q;
        if (q < 2)       *(float2*)(orow + j) = make_float2(mv.x * rn, mv.y * rn);
        else if (q == 2) orow[100] = mv.x * rn;
    }
    __syncthreads();

    for (int idx = tid; idx < SROWS * (CDIM + 1); idx += 256) {
        int rr = idx / (CDIM + 1);
        int jj = idx - rr * (CDIM + 1);
        out[(size_t)r0 * (CDIM + 1) + idx] = sOut[rr * OSTRIDE + jj];
    }
}

extern "C" void kernel_launch(void* const* d_in, const int* in_sizes, int n_in,
                              void* d_out, int out_size) {
    const float* x    = (const float*)d_in[0];
    const float* w    = (const float*)d_in[1];
    const float* xi   = (const float*)d_in[2];
    const float* eta  = (const float*)d_in[3];
    const float* beta = (const float*)d_in[4];
    float* out = (float*)d_out;

    gemm_si_kernel<<<BROWS / GROWS, 64>>>(x, w, xi, eta);
    scan_kernel<<<BROWS / SROWS, 256>>>(beta, out);
}